// round 1
// baseline (speedup 1.0000x reference)
#include <cuda_runtime.h>

#define T_STEPS 1024
#define BATCH   256
#define HID     512
#define NBLK    128
#define UPB     4      // hidden units per block
#define GROWS   16     // gate rows per block (4 units x 4 gates)

// Persistent device state (allocation-free scratch)
__device__ float g_h[2][HID * BATCH];   // transposed: h[k][b]
__device__ float g_c[HID * BATCH];      // transposed: c[j][b]
__device__ float g_zxT[64 * BATCH];     // zx transposed [col][b]
__device__ float g_zeT[16 * BATCH];     // ze logits transposed [col][b]
__device__ unsigned int g_cnt;          // zero-initialized
__device__ unsigned int g_gen;          // zero-initialized

// ---------- helpers ----------
__device__ __forceinline__ void ffma2(unsigned long long& d,
                                      unsigned long long a,
                                      unsigned long long b) {
    asm("fma.rn.f32x2 %0, %1, %2, %0;" : "+l"(d) : "l"(a), "l"(b));
}

__device__ __forceinline__ unsigned long long bcast2(float v) {
    unsigned long long r;
    asm("mov.b64 %0, {%1, %1};" : "=l"(r) : "f"(v));
    return r;
}

__device__ __forceinline__ unsigned long long pack2(float lo, float hi) {
    unsigned long long r;
    asm("mov.b64 %0, {%1, %2};" : "=l"(r) : "f"(lo), "f"(hi));
    return r;
}

__device__ __forceinline__ float lo2(unsigned long long v) {
    return __uint_as_float((unsigned int)v);
}
__device__ __forceinline__ float hi2(unsigned long long v) {
    return __uint_as_float((unsigned int)(v >> 32));
}

__device__ __forceinline__ float sigf(float v) {
    return __fdividef(1.0f, 1.0f + __expf(-v));
}
__device__ __forceinline__ float tanh_fast(float v) {
    return __fdividef(2.0f, 1.0f + __expf(-2.0f * v)) - 1.0f;
}

// Generation-counter grid barrier (all NBLK blocks participate)
__device__ __forceinline__ void gsync() {
    __syncthreads();
    if (threadIdx.x == 0) {
        volatile unsigned int* genp = &g_gen;
        unsigned int g = *genp;
        __threadfence();
        if (atomicAdd(&g_cnt, 1u) == NBLK - 1u) {
            atomicExch(&g_cnt, 0u);
            __threadfence();
            *genp = g + 1u;
        } else {
            while (*genp == g) { }
        }
    }
    __syncthreads();
}

// ---------- main persistent kernel ----------
extern "C" __global__ void __launch_bounds__(BATCH, 1)
lstm_persist(const float* __restrict__ x, const float* __restrict__ a,
             const float* __restrict__ y,
             const float* __restrict__ W_ih, const float* __restrict__ W_hh,
             const float* __restrict__ b_ih, const float* __restrict__ b_hh,
             const float* __restrict__ W_eta, const float* __restrict__ b_eta,
             const float* __restrict__ W_xi,  const float* __restrict__ b_xi,
             const float* __restrict__ W_zeta, const float* __restrict__ b_zeta,
             float* __restrict__ out) {
    __shared__ __align__(16) float sW[HID * GROWS];   // [k][16] = 32 KB
    __shared__ float sWx[GROWS], sWa[GROWS], sWy[GROWS], sB[GROWS];

    const int b   = threadIdx.x;     // one batch row per thread
    const int bid = blockIdx.x;
    const int j0  = bid * UPB;       // first hidden unit owned by this block

    // Load this block's W_hh slice into smem, transposed to [k][local_row].
    // local row l = u*4 + g  ->  global gate row = g*HID + j0 + u
    for (int idx = b; idx < HID * GROWS; idx += BATCH) {
        int k = idx >> 4, l = idx & 15;
        int u = l >> 2,  g = l & 3;
        int row = g * HID + j0 + u;
        sW[k * GROWS + l] = W_hh[row * HID + k];
    }
    if (b < GROWS) {
        int u = b >> 2, g = b & 3;
        int row = g * HID + j0 + u;
        sWx[b] = W_ih[row * 3 + 0];
        sWa[b] = W_ih[row * 3 + 1];
        sWy[b] = W_ih[row * 3 + 2];
        sB[b]  = b_ih[row] + b_hh[row];
    }

    // Zero this block's h/c state slice.
    #pragma unroll
    for (int u = 0; u < UPB; u++) {
        int idx = (j0 + u) * BATCH + b;
        __stcg(&g_h[0][idx], 0.0f);
        g_c[idx] = 0.0f;
    }
    gsync();

    int cur = 0;
    for (int s = 0; s < T_STEPS; s++) {
        const int t = T_STEPS - 1 - s;   // reversed sequence
        const float xv = __ldg(&x[t * BATCH + b]);
        const float av = __ldg(&a[t * BATCH + b]);
        const float yv = __ldg(&y[t * BATCH + b]);

        // g = xproj + h @ W_hh^T ; 16 accumulators as 8 packed f32x2
        unsigned long long acc[8];
        #pragma unroll
        for (int p = 0; p < 8; p++) {
            float f0 = fmaf(sWx[2*p],   xv, fmaf(sWa[2*p],   av, fmaf(sWy[2*p],   yv, sB[2*p])));
            float f1 = fmaf(sWx[2*p+1], xv, fmaf(sWa[2*p+1], av, fmaf(sWy[2*p+1], yv, sB[2*p+1])));
            acc[p] = pack2(f0, f1);
        }

        const float* hin = g_h[cur];
        float hc[8];
        #pragma unroll
        for (int i = 0; i < 8; i++) hc[i] = __ldcg(hin + i * BATCH + b);

        for (int kb = 0; kb < HID; kb += 8) {
            float hn[8];
            const bool more = (kb + 8 < HID);
            #pragma unroll
            for (int i = 0; i < 8; i++)
                hn[i] = more ? __ldcg(hin + (kb + 8 + i) * BATCH + b) : 0.0f;

            #pragma unroll
            for (int i = 0; i < 8; i++) {
                unsigned long long h2 = bcast2(hc[i]);
                const ulonglong2* wr =
                    reinterpret_cast<const ulonglong2*>(sW + (kb + i) * GROWS);
                ulonglong2 w0 = wr[0], w1 = wr[1], w2 = wr[2], w3 = wr[3];
                ffma2(acc[0], h2, w0.x); ffma2(acc[1], h2, w0.y);
                ffma2(acc[2], h2, w1.x); ffma2(acc[3], h2, w1.y);
                ffma2(acc[4], h2, w2.x); ffma2(acc[5], h2, w2.y);
                ffma2(acc[6], h2, w3.x); ffma2(acc[7], h2, w3.y);
            }
            #pragma unroll
            for (int i = 0; i < 8; i++) hc[i] = hn[i];
        }

        // Gates + state update for the 4 owned hidden units.
        float* hout = g_h[cur ^ 1];
        #pragma unroll
        for (int u = 0; u < UPB; u++) {
            float iv = lo2(acc[2*u]);       // row u*4+0 : i
            float fv = hi2(acc[2*u]);       // row u*4+1 : f
            float gv = lo2(acc[2*u + 1]);   // row u*4+2 : g
            float ov = hi2(acc[2*u + 1]);   // row u*4+3 : o
            int idx = (j0 + u) * BATCH + b;
            float co = g_c[idx];
            float cn = sigf(fv) * co + sigf(iv) * tanh_fast(gv);
            g_c[idx] = cn;
            __stcg(&hout[idx], sigf(ov) * tanh_fast(cn));
        }
        gsync();
        cur ^= 1;
    }

    const float* hf = g_h[cur];   // final hidden state (transposed)

    // ---- Phase A: zx columns (blocks 0..63), ze logits (blocks 64..79) ----
    if (bid < 64) {
        const int m = bid;
        float acc = b_xi[m];
        #pragma unroll 8
        for (int k = 0; k < HID; k++)
            acc = fmaf(__ldcg(hf + k * BATCH + b), __ldg(&W_xi[m * HID + k]), acc);
        out[b * 64 + m] = acc;                  // zx at offset 0: [B][64]
        __stcg(&g_zxT[m * BATCH + b], acc);
    } else if (bid < 80) {
        const int e = bid - 64;
        float acc = b_eta[e];
        #pragma unroll 8
        for (int k = 0; k < HID; k++)
            acc = fmaf(__ldcg(hf + k * BATCH + b), __ldg(&W_eta[e * HID + k]), acc);
        __stcg(&g_zeT[e * BATCH + b], acc);
    }
    gsync();

    // ---- Phase B: zy columns (blocks 0..63), ze softmax (block 64) ----
    if (bid < 64) {
        const int m = bid;
        float acc = b_zeta[m];
        const float* wz = W_zeta + m * (HID + 64);
        #pragma unroll 8
        for (int k = 0; k < HID; k++)
            acc = fmaf(__ldcg(hf + k * BATCH + b), __ldg(&wz[k]), acc);
        #pragma unroll
        for (int j = 0; j < 64; j++)
            acc = fmaf(__ldcg(&g_zxT[j * BATCH + b]), __ldg(&wz[HID + j]), acc);
        out[16384 + b * 64 + m] = acc;          // zy at offset 16384: [B][64]
    } else if (bid == 64) {
        float l[16];
        float mx = -1e30f;
        #pragma unroll
        for (int e = 0; e < 16; e++) {
            l[e] = __ldcg(&g_zeT[e * BATCH + b]);
            mx = fmaxf(mx, l[e]);
        }
        float ssum = 0.0f;
        #pragma unroll
        for (int e = 0; e < 16; e++) { l[e] = __expf(l[e] - mx); ssum += l[e]; }
        float inv = __fdividef(1.0f, ssum);
        #pragma unroll
        for (int e = 0; e < 16; e++)
            out[32768 + b * 16 + e] = l[e] * inv;   // ze at offset 32768: [B][16]
    }
}

extern "C" void kernel_launch(void* const* d_in, const int* in_sizes, int n_in,
                              void* d_out, int out_size) {
    const float* x      = (const float*)d_in[0];
    const float* a      = (const float*)d_in[1];
    const float* y      = (const float*)d_in[2];
    const float* W_ih   = (const float*)d_in[3];
    const float* W_hh   = (const float*)d_in[4];
    const float* b_ih   = (const float*)d_in[5];
    const float* b_hh   = (const float*)d_in[6];
    const float* W_eta  = (const float*)d_in[7];
    const float* b_eta  = (const float*)d_in[8];
    const float* W_xi   = (const float*)d_in[9];
    const float* b_xi   = (const float*)d_in[10];
    const float* W_zeta = (const float*)d_in[11];
    const float* b_zeta = (const float*)d_in[12];

    lstm_persist<<<NBLK, BATCH>>>(x, a, y, W_ih, W_hh, b_ih, b_hh,
                                  W_eta, b_eta, W_xi, b_xi, W_zeta, b_zeta,
                                  (float*)d_out);
}

// round 2
// speedup vs baseline: 1.1157x; 1.1157x over previous
#include <cuda_runtime.h>

#define T_STEPS 1024
#define BATCH   256
#define HID     512
#define NBLK    128
#define THREADS 512
#define UPB     4      // hidden units per block
#define GROWS   16     // gate rows per block (4 units x 4 gates)

// Persistent device state (allocation-free scratch)
// h stored as pairs: float2 element p = (h[2p], h[2p+1]) for batch b at [p*BATCH + b]
__device__ float2 g_h[2][(HID / 2) * BATCH];
__device__ float  g_c[HID * BATCH];       // transposed: c[j][b]
__device__ float  g_zxT[64 * BATCH];      // zx transposed [col][b]
__device__ float  g_zeT[16 * BATCH];      // ze logits transposed [col][b]
__device__ unsigned int g_cnt;            // zero-initialized
__device__ unsigned int g_gen;            // zero-initialized

// ---------- helpers ----------
__device__ __forceinline__ void ffma2(unsigned long long& d,
                                      unsigned long long a,
                                      unsigned long long b) {
    asm("fma.rn.f32x2 %0, %1, %2, %0;" : "+l"(d) : "l"(a), "l"(b));
}

__device__ __forceinline__ unsigned long long addf32x2(unsigned long long a,
                                                       unsigned long long b) {
    unsigned long long r;
    asm("add.rn.f32x2 %0, %1, %2;" : "=l"(r) : "l"(a), "l"(b));
    return r;
}

__device__ __forceinline__ unsigned long long bcast2(float v) {
    unsigned long long r;
    asm("mov.b64 %0, {%1, %1};" : "=l"(r) : "f"(v));
    return r;
}

__device__ __forceinline__ unsigned long long pack2(float lo, float hi) {
    unsigned long long r;
    asm("mov.b64 %0, {%1, %2};" : "=l"(r) : "f"(lo), "f"(hi));
    return r;
}

__device__ __forceinline__ float lo2(unsigned long long v) {
    return __uint_as_float((unsigned int)v);
}
__device__ __forceinline__ float hi2(unsigned long long v) {
    return __uint_as_float((unsigned int)(v >> 32));
}

__device__ __forceinline__ float sigf(float v) {
    return __fdividef(1.0f, 1.0f + __expf(-v));
}
__device__ __forceinline__ float tanh_fast(float v) {
    return __fdividef(2.0f, 1.0f + __expf(-2.0f * v)) - 1.0f;
}

// Generation-counter grid barrier (all NBLK blocks participate)
__device__ __forceinline__ void gsync() {
    __syncthreads();
    if (threadIdx.x == 0) {
        volatile unsigned int* genp = &g_gen;
        unsigned int g = *genp;
        __threadfence();
        if (atomicAdd(&g_cnt, 1u) == NBLK - 1u) {
            atomicExch(&g_cnt, 0u);
            __threadfence();
            *genp = g + 1u;
        } else {
            while (*genp == g) { }
        }
    }
    __syncthreads();
}

// ---------- main persistent kernel ----------
extern "C" __global__ void __launch_bounds__(THREADS, 1)
lstm_persist(const float* __restrict__ x, const float* __restrict__ a,
             const float* __restrict__ y,
             const float* __restrict__ W_ih, const float* __restrict__ W_hh,
             const float* __restrict__ b_ih, const float* __restrict__ b_hh,
             const float* __restrict__ W_eta, const float* __restrict__ b_eta,
             const float* __restrict__ W_xi,  const float* __restrict__ b_xi,
             const float* __restrict__ W_zeta, const float* __restrict__ b_zeta,
             float* __restrict__ out) {
    __shared__ __align__(16) float sW[HID * GROWS];          // [k][16] = 32 KB
    __shared__ float sWx[GROWS], sWa[GROWS], sWy[GROWS], sB[GROWS];
    __shared__ unsigned long long sred[BATCH * 8];           // 16 KB reduction buf

    const int tid = threadIdx.x;
    const int b   = tid & (BATCH - 1);   // batch row
    const int hk  = tid >> 8;            // k-half: 0 or 1
    const int bid = blockIdx.x;
    const int j0  = bid * UPB;           // first hidden unit owned by this block

    // Load this block's W_hh slice into smem, transposed to [k][local_row].
    // local row l = u*4 + g  ->  global gate row = g*HID + j0 + u
    for (int idx = tid; idx < HID * GROWS; idx += THREADS) {
        int k = idx >> 4, l = idx & 15;
        int u = l >> 2,  g = l & 3;
        int row = g * HID + j0 + u;
        sW[k * GROWS + l] = W_hh[row * HID + k];
    }
    if (tid < GROWS) {
        int u = tid >> 2, g = tid & 3;
        int row = g * HID + j0 + u;
        sWx[tid] = W_ih[row * 3 + 0];
        sWa[tid] = W_ih[row * 3 + 1];
        sWy[tid] = W_ih[row * 3 + 2];
        sB[tid]  = b_ih[row] + b_hh[row];
    }

    // Zero this block's h/c state slice (half 0 threads only).
    if (hk == 0) {
        float2 z2 = make_float2(0.0f, 0.0f);
        // units j0..j0+3 -> pairs bid*2, bid*2+1
        __stcg(&g_h[0][(bid * 2 + 0) * BATCH + b], z2);
        __stcg(&g_h[0][(bid * 2 + 1) * BATCH + b], z2);
        #pragma unroll
        for (int u = 0; u < UPB; u++) g_c[(j0 + u) * BATCH + b] = 0.0f;
    }
    gsync();

    int cur = 0;
    for (int s = 0; s < T_STEPS; s++) {
        const int t = T_STEPS - 1 - s;   // reversed sequence

        // g = xproj + h @ W_hh^T ; 16 accumulators as 8 packed f32x2
        unsigned long long acc[8];
        if (hk == 0) {
            const float xv = __ldg(&x[t * BATCH + b]);
            const float av = __ldg(&a[t * BATCH + b]);
            const float yv = __ldg(&y[t * BATCH + b]);
            #pragma unroll
            for (int p = 0; p < 8; p++) {
                float f0 = fmaf(sWx[2*p],   xv, fmaf(sWa[2*p],   av, fmaf(sWy[2*p],   yv, sB[2*p])));
                float f1 = fmaf(sWx[2*p+1], xv, fmaf(sWa[2*p+1], av, fmaf(sWy[2*p+1], yv, sB[2*p+1])));
                acc[p] = pack2(f0, f1);
            }
        } else {
            #pragma unroll
            for (int p = 0; p < 8; p++) acc[p] = 0ull;
        }

        // This thread covers k in [hk*256, hk*256+256) == pairs [hk*128, hk*128+128)
        const float2* hin = g_h[cur] + (hk * (HID / 4)) * BATCH + b;  // HID/4 = 128 pairs
        float2 hc[2];
        hc[0] = __ldcg(hin + 0 * BATCH);
        hc[1] = __ldcg(hin + 1 * BATCH);

        const float* sWk = sW + (hk * (HID / 2)) * GROWS;  // this half's first k row

        for (int pb = 0; pb < HID / 4; pb += 2) {
            float2 hn[2];
            const bool more = (pb + 2 < HID / 4);
            #pragma unroll
            for (int i = 0; i < 2; i++)
                hn[i] = more ? __ldcg(hin + (pb + 2 + i) * BATCH)
                             : make_float2(0.0f, 0.0f);

            #pragma unroll
            for (int i = 0; i < 2; i++) {
                const float* wrow = sWk + (2 * (pb + i)) * GROWS;
                {
                    unsigned long long h2 = bcast2(hc[i].x);
                    const ulonglong2* wr = reinterpret_cast<const ulonglong2*>(wrow);
                    ulonglong2 w0 = wr[0], w1 = wr[1], w2 = wr[2], w3 = wr[3];
                    ffma2(acc[0], h2, w0.x); ffma2(acc[1], h2, w0.y);
                    ffma2(acc[2], h2, w1.x); ffma2(acc[3], h2, w1.y);
                    ffma2(acc[4], h2, w2.x); ffma2(acc[5], h2, w2.y);
                    ffma2(acc[6], h2, w3.x); ffma2(acc[7], h2, w3.y);
                }
                {
                    unsigned long long h2 = bcast2(hc[i].y);
                    const ulonglong2* wr = reinterpret_cast<const ulonglong2*>(wrow + GROWS);
                    ulonglong2 w0 = wr[0], w1 = wr[1], w2 = wr[2], w3 = wr[3];
                    ffma2(acc[0], h2, w0.x); ffma2(acc[1], h2, w0.y);
                    ffma2(acc[2], h2, w1.x); ffma2(acc[3], h2, w1.y);
                    ffma2(acc[4], h2, w2.x); ffma2(acc[5], h2, w2.y);
                    ffma2(acc[6], h2, w3.x); ffma2(acc[7], h2, w3.y);
                }
            }
            hc[0] = hn[0];
            hc[1] = hn[1];
        }

        // Cross-half reduction through smem.
        if (hk == 1) {
            #pragma unroll
            for (int p = 0; p < 8; p++) sred[b * 8 + p] = acc[p];
        }
        __syncthreads();

        if (hk == 0) {
            #pragma unroll
            for (int p = 0; p < 8; p++) acc[p] = addf32x2(acc[p], sred[b * 8 + p]);

            // Gates + state update for the 4 owned hidden units.
            float hv[UPB];
            #pragma unroll
            for (int u = 0; u < UPB; u++) {
                float iv = lo2(acc[2*u]);       // row u*4+0 : i
                float fv = hi2(acc[2*u]);       // row u*4+1 : f
                float gv = lo2(acc[2*u + 1]);   // row u*4+2 : g
                float ov = hi2(acc[2*u + 1]);   // row u*4+3 : o
                int idx = (j0 + u) * BATCH + b;
                float co = g_c[idx];
                float cn = sigf(fv) * co + sigf(iv) * tanh_fast(gv);
                g_c[idx] = cn;
                hv[u] = sigf(ov) * tanh_fast(cn);
            }
            float2* hout = g_h[cur ^ 1];
            __stcg(&hout[(bid * 2 + 0) * BATCH + b], make_float2(hv[0], hv[1]));
            __stcg(&hout[(bid * 2 + 1) * BATCH + b], make_float2(hv[2], hv[3]));
        }
        gsync();
        cur ^= 1;
    }

    const float2* hf = g_h[cur];   // final hidden state (pair layout)

    // ---- Phase A: zx columns (blocks 0..63), ze logits (blocks 64..79) ----
    if (hk == 0) {
        if (bid < 64) {
            const int m = bid;
            float acc = b_xi[m];
            const float* wm = W_xi + m * HID;
            #pragma unroll 8
            for (int p = 0; p < HID / 2; p++) {
                float2 hv = __ldcg(hf + p * BATCH + b);
                acc = fmaf(hv.x, __ldg(&wm[2*p]), acc);
                acc = fmaf(hv.y, __ldg(&wm[2*p + 1]), acc);
            }
            out[b * 64 + m] = acc;                  // zx at offset 0: [B][64]
            __stcg(&g_zxT[m * BATCH + b], acc);
        } else if (bid < 80) {
            const int e = bid - 64;
            float acc = b_eta[e];
            const float* we = W_eta + e * HID;
            #pragma unroll 8
            for (int p = 0; p < HID / 2; p++) {
                float2 hv = __ldcg(hf + p * BATCH + b);
                acc = fmaf(hv.x, __ldg(&we[2*p]), acc);
                acc = fmaf(hv.y, __ldg(&we[2*p + 1]), acc);
            }
            __stcg(&g_zeT[e * BATCH + b], acc);
        }
    }
    gsync();

    // ---- Phase B: zy columns (blocks 0..63), ze softmax (block 64) ----
    if (hk == 0) {
        if (bid < 64) {
            const int m = bid;
            float acc = b_zeta[m];
            const float* wz = W_zeta + m * (HID + 64);
            #pragma unroll 8
            for (int p = 0; p < HID / 2; p++) {
                float2 hv = __ldcg(hf + p * BATCH + b);
                acc = fmaf(hv.x, __ldg(&wz[2*p]), acc);
                acc = fmaf(hv.y, __ldg(&wz[2*p + 1]), acc);
            }
            #pragma unroll
            for (int j = 0; j < 64; j++)
                acc = fmaf(__ldcg(&g_zxT[j * BATCH + b]), __ldg(&wz[HID + j]), acc);
            out[16384 + b * 64 + m] = acc;          // zy at offset 16384: [B][64]
        } else if (bid == 64) {
            float l[16];
            float mx = -1e30f;
            #pragma unroll
            for (int e = 0; e < 16; e++) {
                l[e] = __ldcg(&g_zeT[e * BATCH + b]);
                mx = fmaxf(mx, l[e]);
            }
            float ssum = 0.0f;
            #pragma unroll
            for (int e = 0; e < 16; e++) { l[e] = __expf(l[e] - mx); ssum += l[e]; }
            float inv = __fdividef(1.0f, ssum);
            #pragma unroll
            for (int e = 0; e < 16; e++)
                out[32768 + b * 16 + e] = l[e] * inv;   // ze at offset 32768: [B][16]
        }
    }
}

extern "C" void kernel_launch(void* const* d_in, const int* in_sizes, int n_in,
                              void* d_out, int out_size) {
    const float* x      = (const float*)d_in[0];
    const float* a      = (const float*)d_in[1];
    const float* y      = (const float*)d_in[2];
    const float* W_ih   = (const float*)d_in[3];
    const float* W_hh   = (const float*)d_in[4];
    const float* b_ih   = (const float*)d_in[5];
    const float* b_hh   = (const float*)d_in[6];
    const float* W_eta  = (const float*)d_in[7];
    const float* b_eta  = (const float*)d_in[8];
    const float* W_xi   = (const float*)d_in[9];
    const float* b_xi   = (const float*)d_in[10];
    const float* W_zeta = (const float*)d_in[11];
    const float* b_zeta = (const float*)d_in[12];

    lstm_persist<<<NBLK, THREADS>>>(x, a, y, W_ih, W_hh, b_ih, b_hh,
                                    W_eta, b_eta, W_xi, b_xi, W_zeta, b_zeta,
                                    (float*)d_out);
}